// round 16
// baseline (speedup 1.0000x reference)
#include <cuda_runtime.h>
#include <math.h>

#define HID   64
#define HEADS 4
#define HDIM  16
#define NMOL  2048
#define NPROT 4096
#define EMOL  32768
#define EPROT 131072
#define BB    32
#define SPLITS 16
#define QT    128
#define KT    64

typedef unsigned long long ull;

// ---------------- scratch (device globals) -----------------------------------
__device__ float g_xm[NMOL*HID];
__device__ float g_xp[NPROT*HID];
__device__ float g_em[EMOL*HID];      // permuted (CSR slot order)
__device__ float g_ep[EPROT*HID];     // permuted
__device__ float g_hm[NMOL*HID];      // ping-pong partner of g_xm
__device__ float g_hp[NPROT*HID];
__device__ float g_q1[NMOL*HID];
__device__ float g_k1[NPROT*HID];
__device__ float g_v1[NPROT*HID];
__device__ float g_q2[NPROT*HID];
__device__ float g_k2[NMOL*HID];
__device__ float g_v2[NMOL*HID];
__device__ float g_part1[(size_t)NMOL*HEADS*SPLITS*18];
__device__ float g_part2[(size_t)NPROT*HEADS*SPLITS*18];
// CSR scratch (zero-initialized at load; scan re-zeroes cnt each run)
__device__ int g_mcnt[NMOL+1];
__device__ int g_moff[NMOL+1];
__device__ int g_mcur[NMOL];
__device__ int g_msrc[EMOL];
__device__ int g_mpos[EMOL];
__device__ int g_pcnt[NPROT+1];
__device__ int g_poff[NPROT+1];
__device__ int g_pcur[NPROT];
__device__ int g_psrc[EPROT];
__device__ int g_ppos[EPROT];

// ---------------- f32x2 helpers (flash only) ----------------------------------
__device__ __forceinline__ ull pk2(float a, float b) {
    ull r; asm("mov.b64 %0, {%1,%2};" : "=l"(r) : "f"(a), "f"(b)); return r;
}
__device__ __forceinline__ void upk2(float& a, float& b, ull r) {
    asm("mov.b64 {%0,%1}, %2;" : "=f"(a), "=f"(b) : "l"(r));
}
__device__ __forceinline__ ull ffma2(ull a, ull b, ull c) {
    ull d; asm("fma.rn.f32x2 %0, %1, %2, %3;" : "=l"(d) : "l"(a), "l"(b), "l"(c)); return d;
}
__device__ __forceinline__ ull fmul2(ull a, ull b) {
    ull d; asm("mul.rn.f32x2 %0, %1, %2;" : "=l"(d) : "l"(a), "l"(b)); return d;
}
union LD { float4 f4; ulonglong2 u2; };

// ---------------- CSR build: hist / scan / scatter ----------------------------
__global__ void hist_fused(const int* __restrict__ mdst, const int* __restrict__ pdst,
                           int* __restrict__ mcnt, int* __restrict__ pcnt) {
    int e = blockIdx.x*blockDim.x + threadIdx.x;
    if (e < EMOL) atomicAdd(&mcnt[mdst[e]], 1);
    else if (e < EMOL + EPROT) atomicAdd(&pcnt[pdst[e - EMOL]], 1);
}

__global__ void scan_fused(int* __restrict__ mcnt, int* __restrict__ moff, int* __restrict__ mcur,
                           int* __restrict__ pcnt, int* __restrict__ poff, int* __restrict__ pcur) {
    int* cnt; int* off; int* cur; int N;
    if (blockIdx.x == 0) { cnt = mcnt; off = moff; cur = mcur; N = NMOL; }
    else                 { cnt = pcnt; off = poff; cur = pcur; N = NPROT; }
    __shared__ int wsum[32];
    int t = threadIdx.x, lane = t & 31, wid = t >> 5;
    int base = t*4;
    int v[4];
    #pragma unroll
    for (int i = 0; i < 4; i++) v[i] = (base+i < N) ? cnt[base+i] : 0;
    #pragma unroll
    for (int i = 0; i < 4; i++) if (base+i < N) cnt[base+i] = 0;
    int local = v[0]+v[1]+v[2]+v[3];
    int sc = local;
    #pragma unroll
    for (int o = 1; o < 32; o <<= 1) {
        int x = __shfl_up_sync(~0u, sc, o);
        if (lane >= o) sc += x;
    }
    if (lane == 31) wsum[wid] = sc;
    __syncthreads();
    if (wid == 0) {
        int x = wsum[lane];
        #pragma unroll
        for (int o = 1; o < 32; o <<= 1) {
            int y = __shfl_up_sync(~0u, x, o);
            if (lane >= o) x += y;
        }
        wsum[lane] = x;
    }
    __syncthreads();
    int excl = sc - local + (wid ? wsum[wid-1] : 0);
    #pragma unroll
    for (int i = 0; i < 4; i++) {
        if (base+i < N) { off[base+i] = excl; cur[base+i] = excl; }
        excl += v[i];
    }
    if (t == 1023) off[N] = wsum[31];
}

__global__ void scatter_fused(const int* __restrict__ mei, const int* __restrict__ pei,
                              int* __restrict__ mcur, int* __restrict__ msrc, int* __restrict__ mpos,
                              int* __restrict__ pcur, int* __restrict__ psrc, int* __restrict__ ppos) {
    int e = blockIdx.x*blockDim.x + threadIdx.x;
    if (e < EMOL) {
        int p = atomicAdd(&mcur[mei[EMOL + e]], 1);
        msrc[p] = mei[e];
        mpos[e] = p;
    } else if (e < EMOL + EPROT) {
        int ee = e - EMOL;
        int p = atomicAdd(&pcur[pei[EPROT + ee]], 1);
        psrc[p] = pei[ee];
        ppos[ee] = p;
    }
}

// ---------------- fused embeddings: 64 rows/block, float4 input loads --------
struct EmbedArgs {
    const float* in[4]; const float* W[4]; const float* b[4];
    float* out[4]; const int* pos[4]; int K[4]; int ofs[5];
};

template<int K4>
__device__ __forceinline__ void embed_body(const float* __restrict__ ins,
                                           const float* __restrict__ ws,
                                           int rl, int c, float4* acc) {
    #pragma unroll
    for (int k4 = 0; k4 < K4; k4++) {
        float4 w0 = ((const float4*)ws)[(4*k4+0)*16 + c];
        float4 w1 = ((const float4*)ws)[(4*k4+1)*16 + c];
        float4 w2 = ((const float4*)ws)[(4*k4+2)*16 + c];
        float4 w3 = ((const float4*)ws)[(4*k4+3)*16 + c];
        #pragma unroll
        for (int j = 0; j < 4; j++) {
            float4 iv = ((const float4*)(ins + (rl + 16*j)*16))[k4];
            acc[j].x = fmaf(iv.x, w0.x, acc[j].x); acc[j].y = fmaf(iv.x, w0.y, acc[j].y);
            acc[j].z = fmaf(iv.x, w0.z, acc[j].z); acc[j].w = fmaf(iv.x, w0.w, acc[j].w);
            acc[j].x = fmaf(iv.y, w1.x, acc[j].x); acc[j].y = fmaf(iv.y, w1.y, acc[j].y);
            acc[j].z = fmaf(iv.y, w1.z, acc[j].z); acc[j].w = fmaf(iv.y, w1.w, acc[j].w);
            acc[j].x = fmaf(iv.z, w2.x, acc[j].x); acc[j].y = fmaf(iv.z, w2.y, acc[j].y);
            acc[j].z = fmaf(iv.z, w2.z, acc[j].z); acc[j].w = fmaf(iv.z, w2.w, acc[j].w);
            acc[j].x = fmaf(iv.w, w3.x, acc[j].x); acc[j].y = fmaf(iv.w, w3.y, acc[j].y);
            acc[j].z = fmaf(iv.w, w3.z, acc[j].z); acc[j].w = fmaf(iv.w, w3.w, acc[j].w);
        }
    }
}

__global__ void embed_fused(EmbedArgs a) {
    __shared__ float ws[16*64];    // K rows staged, rows K..15 zeroed
    __shared__ float ins[64*16];   // 64 rows, K cols staged, rest zeroed
    __shared__ float bs[64];
    int bid = blockIdx.x;
    int t;
    if      (bid < a.ofs[1]) t = 0;
    else if (bid < a.ofs[2]) t = 1;
    else if (bid < a.ofs[3]) t = 2;
    else                     t = 3;
    int K = a.K[t];
    int rel = bid - a.ofs[t];
    int tid = threadIdx.x;
    for (int i = tid; i < K*64; i += 256) ws[i] = a.W[t][i];
    for (int i = tid; i < (16-K)*64; i += 256) ws[K*64 + i] = 0.f;   // zero-pad weight rows
    if (tid < 64) bs[tid] = a.b[t][tid];
    {   // zero ins, then stage 64 rows coalesced
        float4* iz = (float4*)ins;
        iz[tid] = make_float4(0.f, 0.f, 0.f, 0.f);                    // 256 f4 = 1024 floats
        __syncthreads();
        const float* inb = a.in[t] + (size_t)rel*64*K;
        for (int i = tid; i < 64*K; i += 256) ins[(i/K)*16 + (i%K)] = inb[i];
    }
    __syncthreads();
    int c = tid & 15, rl = tid >> 4;
    float4 acc[4];
    #pragma unroll
    for (int j = 0; j < 4; j++) acc[j] = ((const float4*)bs)[c];
    if (K == 11)      embed_body<3>(ins, ws, rl, c, acc);   // covers k 0..11 (pad zero)
    else if (K == 15) embed_body<4>(ins, ws, rl, c, acc);   // covers k 0..15
    else              embed_body<3>(ins, ws, rl, c, acc);   // K=10, covers 0..11
    const int* pos = a.pos[t];
    float4* outp = (float4*)a.out[t];
    #pragma unroll
    for (int j = 0; j < 4; j++) {
        int row = rel*64 + rl + 16*j;
        int orow = pos ? pos[row] : row;
        outp[(size_t)orow*16 + c] = acc[j];
    }
}

// ---------------- fused GINE layer: 512 threads, float2 gather + MLP ---------
struct GineArgs {
    const float* x[2]; const float* e[2];
    const int* off[2]; const int* srcs[2];
    const float* W1[2]; const float* b1[2]; const float* W2[2]; const float* b2[2];
    float* xout[2]; int nblk0;
};
__global__ void gine_fused(GineArgs a) {
    __shared__ float w1s[64*64];
    __shared__ float w2s[64*64];
    __shared__ float hs[16][64];
    __shared__ float ts[16][64];
    int g = (blockIdx.x < a.nblk0) ? 0 : 1;
    int bbase = ((g ? blockIdx.x - a.nblk0 : blockIdx.x)) * 16;
    int tid = threadIdx.x;     // 512
    for (int i = tid; i < 64*64; i += 512) { w1s[i] = a.W1[g][i]; w2s[i] = a.W2[g][i]; }
    const float* x    = a.x[g];
    const float* e    = a.e[g];
    const int*   off  = a.off[g];
    const int*   srcs = a.srcs[g];
    // gather: all 16 nodes concurrent, 32 threads/node, float2 per thread
    {
        int r = tid >> 5;          // node slot 0..15
        int c = tid & 31;          // float2 column 0..31
        int node = bbase + r;
        const float2* x2 = (const float2*)x;
        const float2* e2 = (const float2*)e;
        float2 acc = __ldg(x2 + (size_t)node*32 + c);
        int jb = off[node], je = off[node+1];
        #pragma unroll 8
        for (int j = jb; j < je; j++) {
            int s = __ldg(srcs + j);
            float2 xv = __ldg(x2 + (size_t)s*32 + c);
            float2 ev = __ldg(e2 + (size_t)j*32 + c);
            acc.x += fmaxf(xv.x + ev.x, 0.f);
            acc.y += fmaxf(xv.y + ev.y, 0.f);
        }
        ((float2*)hs[r])[c] = acc;
    }
    __syncthreads();
    // MLP: 16 rows x 32 col-pairs (float2 per thread)
    int r = tid >> 5, c = tid & 31;
    float2 acc = ((const float2*)a.b1[g])[c];
    #pragma unroll
    for (int k = 0; k < 64; k++) {
        float hv = hs[r][k];
        float2 w = ((const float2*)(w1s + k*64))[c];
        acc.x = fmaf(hv, w.x, acc.x);
        acc.y = fmaf(hv, w.y, acc.y);
    }
    acc.x = fmaxf(acc.x, 0.f); acc.y = fmaxf(acc.y, 0.f);
    ((float2*)ts[r])[c] = acc;
    __syncthreads();
    float2 acc2 = ((const float2*)a.b2[g])[c];
    #pragma unroll
    for (int k = 0; k < 64; k++) {
        float hv = ts[r][k];
        float2 w = ((const float2*)(w2s + k*64))[c];
        acc2.x = fmaf(hv, w.x, acc2.x);
        acc2.y = fmaf(hv, w.y, acc2.y);
    }
    acc2.x = fmaxf(acc2.x, 0.f); acc2.y = fmaxf(acc2.y, 0.f);
    ((float2*)(a.xout[g] + (size_t)(bbase + r)*HID))[c] = acc2;
}

// ---------------- fused QKV linears: 64 rows/block, 4x4 register tile --------
struct QKVArgs {
    const float* in[6]; const float* W[6]; const float* b[6];
    float* out[6]; int ofs[7];
};
__global__ void qkv_fused(QKVArgs a) {
    __shared__ float ws[64*64];
    __shared__ float ins[64*64];
    __shared__ float bs[64];
    int bid = blockIdx.x;
    int t = 5;
    #pragma unroll
    for (int i = 5; i >= 1; i--) if (bid < a.ofs[i]) t = i - 1;
    int rel = bid - a.ofs[t];
    int tid = threadIdx.x;
    {
        const float4* wg = (const float4*)a.W[t];
        float4* wsh = (float4*)ws;
        #pragma unroll
        for (int i = 0; i < 4; i++) wsh[tid + 256*i] = wg[tid + 256*i];
    }
    if (tid < 64) bs[tid] = a.b[t][tid];
    {
        const float4* ig = (const float4*)(a.in[t] + (size_t)rel*64*64);
        float4* ish = (float4*)ins;
        #pragma unroll
        for (int i = 0; i < 4; i++) ish[tid + 256*i] = ig[tid + 256*i];
    }
    __syncthreads();
    int c = tid & 15, rl = tid >> 4;
    float4 acc[4];
    #pragma unroll
    for (int j = 0; j < 4; j++) acc[j] = ((const float4*)bs)[c];
    #pragma unroll 16
    for (int k = 0; k < 64; k++) {
        float4 w = ((const float4*)ws)[k*16 + c];
        #pragma unroll
        for (int j = 0; j < 4; j++) {
            float iv = ins[(rl + 16*j)*64 + k];
            acc[j].x = fmaf(iv, w.x, acc[j].x);
            acc[j].y = fmaf(iv, w.y, acc[j].y);
            acc[j].z = fmaf(iv, w.z, acc[j].z);
            acc[j].w = fmaf(iv, w.w, acc[j].w);
        }
    }
    float4* outp = (float4*)a.out[t];
    #pragma unroll
    for (int j = 0; j < 4; j++)
        outp[(size_t)(rel*64 + rl + 16*j)*16 + c] = acc[j];
}

// ---------------- flash attention: 4-key batched max, base-2, f32x2 ----------
__global__ void flash_fused(const float* __restrict__ Q1, const float* __restrict__ K1,
                            const float* __restrict__ V1, const float* __restrict__ Q2,
                            const float* __restrict__ K2, const float* __restrict__ V2,
                            float* __restrict__ part1, float* __restrict__ part2) {
    __shared__ float4 sk[KT][4];
    __shared__ float4 sv[KT][4];
    const float *Q, *K, *V; float* part; int Nk, qblk;
    if (blockIdx.x < NMOL/QT) { Q = Q1; K = K1; V = V1; part = part1; Nk = NPROT; qblk = blockIdx.x; }
    else                      { Q = Q2; K = K2; V = V2; part = part2; Nk = NMOL;  qblk = blockIdx.x - NMOL/QT; }
    int h  = blockIdx.y;
    int sp = blockIdx.z;
    int chunk = Nk / SPLITS;
    int q  = qblk*QT + threadIdx.x;
    int k0 = sp*chunk;
    int k1 = k0 + chunk;
    const float QSCALE = 0.25f * 1.4426950408889634f;   // 1/sqrt(16) * log2(e)
    ull q2[8];
    {
        const float4* qp = (const float4*)(Q + (size_t)q*HID + h*HDIM);
        #pragma unroll
        for (int i = 0; i < 4; i++) {
            float4 tq = qp[i];
            q2[2*i]   = pk2(tq.x*QSCALE, tq.y*QSCALE);
            q2[2*i+1] = pk2(tq.z*QSCALE, tq.w*QSCALE);
        }
    }
    float m = -1e30f, l = 0.f;      // m in log2 domain
    ull o2[8];
    #pragma unroll
    for (int i = 0; i < 8; i++) o2[i] = 0ull;

    for (int kt = k0; kt < k1; kt += KT) {
        __syncthreads();
        for (int idx = threadIdx.x; idx < KT*4; idx += QT) {
            int row = idx >> 2, c = idx & 3;
            sk[row][c] = ((const float4*)(K + (size_t)(kt+row)*HID + h*HDIM))[c];
            sv[row][c] = ((const float4*)(V + (size_t)(kt+row)*HID + h*HDIM))[c];
        }
        __syncthreads();
        for (int jj = 0; jj < KT; jj += 4) {
            float sc[4];
            #pragma unroll
            for (int t = 0; t < 4; t++) {
                LD kr[4];
                #pragma unroll
                for (int c = 0; c < 4; c++) kr[c].f4 = sk[jj+t][c];
                ull acc = 0ull;
                #pragma unroll
                for (int c = 0; c < 4; c++) {
                    acc = ffma2(q2[2*c],   kr[c].u2.x, acc);
                    acc = ffma2(q2[2*c+1], kr[c].u2.y, acc);
                }
                float lo, hi; upk2(lo, hi, acc);
                sc[t] = lo + hi;                   // log2 domain
            }
            float mx = fmaxf(fmaxf(sc[0], sc[1]), fmaxf(sc[2], sc[3]));
            if (mx > m) {
                float alpha = exp2f(m - mx);
                l *= alpha;
                ull a2 = pk2(alpha, alpha);
                #pragma unroll
                for (int i = 0; i < 8; i++) o2[i] = fmul2(o2[i], a2);
                m = mx;
            }
            #pragma unroll
            for (int t = 0; t < 4; t++) {
                float p = exp2f(sc[t] - m);
                l += p;
                ull p2 = pk2(p, p);
                #pragma unroll
                for (int c = 0; c < 4; c++) {
                    LD vr; vr.f4 = sv[jj+t][c];
                    o2[2*c]   = ffma2(p2, vr.u2.x, o2[2*c]);
                    o2[2*c+1] = ffma2(p2, vr.u2.y, o2[2*c+1]);
                }
            }
        }
    }
    float* pp = part + (((size_t)q*HEADS + h)*SPLITS + sp)*18;
    pp[0] = m; pp[1] = l;
    #pragma unroll
    for (int i = 0; i < 8; i++) upk2(pp[2+2*i], pp[3+2*i], o2[i]);
}

// ---------------- combine split-KV partials + residual (base-2 domain) -------
__global__ void combine_fused(const float* __restrict__ part1, const float* __restrict__ part2,
                              const float* __restrict__ xm, const float* __restrict__ xp,
                              float* __restrict__ Hm, float* __restrict__ Hp) {
    int idx = blockIdx.x*blockDim.x + threadIdx.x;
    const float* part; const float* x; float* H;
    if (idx < NMOL*HEADS) { part = part1; x = xm; H = Hm; }
    else { idx -= NMOL*HEADS; if (idx >= NPROT*HEADS) return; part = part2; x = xp; H = Hp; }
    int q = idx >> 2, h = idx & 3;
    const float* pp = part + (size_t)idx*SPLITS*18;
    float M = -1e30f;
    #pragma unroll
    for (int sp = 0; sp < SPLITS; sp++) M = fmaxf(M, pp[sp*18]);
    float L = 0.f;
    float O[HDIM];
    #pragma unroll
    for (int i = 0; i < HDIM; i++) O[i] = 0.f;
    #pragma unroll
    for (int sp = 0; sp < SPLITS; sp++) {
        float w = exp2f(pp[sp*18] - M);
        L += w * pp[sp*18 + 1];
        #pragma unroll
        for (int i = 0; i < HDIM; i++) O[i] = fmaf(w, pp[sp*18 + 2 + i], O[i]);
    }
    float inv = 1.f / L;
    #pragma unroll
    for (int i = 0; i < HDIM; i++)
        H[(size_t)q*HID + h*HDIM + i] = x[(size_t)q*HID + h*HDIM + i] + O[i]*inv;
}

// ---------------- fused pooling + head MLP: one block per batch element ------
__global__ void pool_final(const float* __restrict__ Hm, const float* __restrict__ Hp,
                           const int* __restrict__ mbatch, const int* __restrict__ pbatch,
                           const float* __restrict__ fc1W, const float* __restrict__ fc1b,
                           const float* __restrict__ fc2W, const float* __restrict__ fc2b,
                           float* __restrict__ out) {
    __shared__ float zs[2*HID];
    __shared__ float wpart[2];
    int b = blockIdx.x;
    int f = threadIdx.x;   // 64
    {
        int lo = 0, hi = NMOL;
        while (lo < hi) { int mid = (lo+hi) >> 1; if (mbatch[mid] < b) lo = mid+1; else hi = mid; }
        int lo2 = lo, hi2 = NMOL;
        while (lo2 < hi2) { int mid = (lo2+hi2) >> 1; if (mbatch[mid] < b+1) lo2 = mid+1; else hi2 = mid; }
        float s = 0.f;
        for (int r = lo; r < lo2; r++) s += Hm[(size_t)r*HID + f];
        zs[f] = s / fmaxf((float)(lo2 - lo), 1.f);
    }
    {
        int lo = 0, hi = NPROT;
        while (lo < hi) { int mid = (lo+hi) >> 1; if (pbatch[mid] < b) lo = mid+1; else hi = mid; }
        int lo2 = lo, hi2 = NPROT;
        while (lo2 < hi2) { int mid = (lo2+hi2) >> 1; if (pbatch[mid] < b+1) lo2 = mid+1; else hi2 = mid; }
        float s = 0.f;
        for (int r = lo; r < lo2; r++) s += Hp[(size_t)r*HID + f];
        zs[HID + f] = s / fmaxf((float)(lo2 - lo), 1.f);
    }
    __syncthreads();
    float acc = fc1b[f];
    #pragma unroll 8
    for (int k = 0; k < 2*HID; k++) acc = fmaf(zs[k], fc1W[k*HID + f], acc);
    float r = fmaxf(acc, 0.f) * fc2W[f];
    #pragma unroll
    for (int off = 16; off; off >>= 1) r += __shfl_down_sync(0xffffffffu, r, off);
    if ((f & 31) == 0) wpart[f >> 5] = r;
    __syncthreads();
    if (f == 0) out[b] = 1.f / (1.f + __expf(-(wpart[0] + wpart[1] + fc2b[0])));
}

// =============================================================================
extern "C" void kernel_launch(void* const* d_in, const int* in_sizes, int n_in,
                              void* d_out, int out_size) {
    static const int sig_map[32]   = { 0,1,2,3, 4,5,6,7, 8,9,10,11, 12,13,14,15,
                                       16,17,18,19, 20,21,22,23, 24,25,26,27, 28,29,30,31 };
    static const int setup_map[32] = { 0,1,2,3, 8,9,10,11, 12,13,14,15, 16,17,18,19,
                                       20,21,22,23, 24,25,26,27, 28,29,30,31, 4,5,6,7 };
    const int* map = (in_sizes[4] == 2*EMOL) ? setup_map : sig_map;
    #define IN(p) ((const float*)d_in[map[(p)]])
    #define INI(p) ((const int*)d_in[map[(p)]])

    const float *mol_x = IN(0), *prot_x = IN(1), *mol_eattr = IN(2), *prot_eattr = IN(3);
    const float *nlmW = IN(4), *nlmb = IN(5), *nlpW = IN(6), *nlpb = IN(7);
    const float *elmW = IN(8), *elmb = IN(9), *elpW = IN(10), *elpb = IN(11);
    const float *mcW1 = IN(12), *mcb1 = IN(13), *mcW2 = IN(14), *mcb2 = IN(15);
    const float *pcW1 = IN(16), *pcb1 = IN(17), *pcW2 = IN(18), *pcb2 = IN(19);
    const float *ampW = IN(20), *ampb = IN(21), *apmW = IN(22), *apmb = IN(23);
    const float *fc1W = IN(24), *fc1b = IN(25), *fc2W = IN(26), *fc2b = IN(27);
    const int *mei = INI(28), *pei = INI(29), *mbatch = INI(30), *pbatch = INI(31);
    float* out = (float*)d_out;

    float *xm, *xp, *em, *ep, *hm, *hp, *q1, *k1, *v1, *q2, *k2, *v2, *part1, *part2;
    int *mcnt, *moff, *mcur, *msrc, *mpos, *pcnt, *poff, *pcur, *psrc, *ppos;
    cudaGetSymbolAddress((void**)&xm, g_xm);
    cudaGetSymbolAddress((void**)&xp, g_xp);
    cudaGetSymbolAddress((void**)&em, g_em);
    cudaGetSymbolAddress((void**)&ep, g_ep);
    cudaGetSymbolAddress((void**)&hm, g_hm);
    cudaGetSymbolAddress((void**)&hp, g_hp);
    cudaGetSymbolAddress((void**)&q1, g_q1);
    cudaGetSymbolAddress((void**)&k1, g_k1);
    cudaGetSymbolAddress((void**)&v1, g_v1);
    cudaGetSymbolAddress((void**)&q2, g_q2);
    cudaGetSymbolAddress((void**)&k2, g_k2);
    cudaGetSymbolAddress((void**)&v2, g_v2);
    cudaGetSymbolAddress((void**)&part1, g_part1);
    cudaGetSymbolAddress((void**)&part2, g_part2);
    cudaGetSymbolAddress((void**)&mcnt, g_mcnt);
    cudaGetSymbolAddress((void**)&moff, g_moff);
    cudaGetSymbolAddress((void**)&mcur, g_mcur);
    cudaGetSymbolAddress((void**)&msrc, g_msrc);
    cudaGetSymbolAddress((void**)&mpos, g_mpos);
    cudaGetSymbolAddress((void**)&pcnt, g_pcnt);
    cudaGetSymbolAddress((void**)&poff, g_poff);
    cudaGetSymbolAddress((void**)&pcur, g_pcur);
    cudaGetSymbolAddress((void**)&psrc, g_psrc);
    cudaGetSymbolAddress((void**)&ppos, g_ppos);

    const int TB = 256;

    // --- 1-3: CSR build
    hist_fused<<<(EMOL + EPROT + TB - 1)/TB, TB>>>(mei + EMOL, pei + EPROT, mcnt, pcnt);
    scan_fused<<<2, 1024>>>(mcnt, moff, mcur, pcnt, poff, pcur);
    scatter_fused<<<(EMOL + EPROT + TB - 1)/TB, TB>>>(mei, pei, mcur, msrc, mpos, pcur, psrc, ppos);

    // --- 4: all embeddings, 64 rows/block (edge outputs in CSR order)
    {
        EmbedArgs a;
        a.in[0] = mol_x;     a.W[0] = nlmW; a.b[0] = nlmb; a.out[0] = xm; a.pos[0] = nullptr; a.K[0] = 11;
        a.in[1] = prot_x;    a.W[1] = nlpW; a.b[1] = nlpb; a.out[1] = xp; a.pos[1] = nullptr; a.K[1] = 15;
        a.in[2] = mol_eattr; a.W[2] = elmW; a.b[2] = elmb; a.out[2] = em; a.pos[2] = mpos;    a.K[2] = 10;
        a.in[3] = prot_eattr;a.W[3] = elpW; a.b[3] = elpb; a.out[3] = ep; a.pos[3] = ppos;    a.K[3] = 10;
        a.ofs[0] = 0; a.ofs[1] = NMOL/64; a.ofs[2] = a.ofs[1] + NPROT/64;
        a.ofs[3] = a.ofs[2] + EMOL/64; a.ofs[4] = a.ofs[3] + EPROT/64;
        embed_fused<<<a.ofs[4], TB>>>(a);
    }

    // --- 5-7: GINE layers, 512 threads/block, ping-pong buffers (in != out)
    for (int l = 0; l < 3; l++) {
        const float* im = (l & 1) ? hm : xm;
        const float* ip = (l & 1) ? hp : xp;
        float* om = (l & 1) ? xm : hm;
        float* op = (l & 1) ? xp : hp;
        GineArgs a;
        a.x[0] = im; a.e[0] = em; a.off[0] = moff; a.srcs[0] = msrc;
        a.W1[0] = mcW1 + l*4096; a.b1[0] = mcb1 + l*64; a.W2[0] = mcW2 + l*4096; a.b2[0] = mcb2 + l*64;
        a.xout[0] = om;
        a.x[1] = ip; a.e[1] = ep; a.off[1] = poff; a.srcs[1] = psrc;
        a.W1[1] = pcW1 + l*4096; a.b1[1] = pcb1 + l*64; a.W2[1] = pcW2 + l*4096; a.b2[1] = pcb2 + l*64;
        a.xout[1] = op;
        a.nblk0 = NMOL/16;
        gine_fused<<<NMOL/16 + NPROT/16, 512>>>(a);
    }
    // post-conv features: hm (mol), hp (prot)

    // --- 8: all six QKV linears, 64 rows/block
    {
        QKVArgs a;
        a.in[0] = hm; a.W[0] = ampW;        a.b[0] = ampb;       a.out[0] = q1;
        a.in[1] = hp; a.W[1] = ampW + 4096; a.b[1] = ampb + 64;  a.out[1] = k1;
        a.in[2] = hp; a.W[2] = ampW + 8192; a.b[2] = ampb + 128; a.out[2] = v1;
        a.in[3] = hp; a.W[3] = apmW;        a.b[3] = apmb;       a.out[3] = q2;
        a.in[4] = hm; a.W[4] = apmW + 4096; a.b[4] = apmb + 64;  a.out[4] = k2;
        a.in[5] = hm; a.W[5] = apmW + 8192; a.b[5] = apmb + 128; a.out[5] = v2;
        int nb[6] = { NMOL/64, NPROT/64, NPROT/64, NPROT/64, NMOL/64, NMOL/64 };
        a.ofs[0] = 0;
        for (int i = 0; i < 6; i++) a.ofs[i+1] = a.ofs[i] + nb[i];
        qkv_fused<<<a.ofs[6], TB>>>(a);
    }

    // --- 9: flash attention, both directions (SPLITS=16 wave smoothing)
    {
        dim3 grid(NMOL/QT + NPROT/QT, HEADS, SPLITS);
        flash_fused<<<grid, QT>>>(q1, k1, v1, q2, k2, v2, part1, part2);
    }

    // --- 10: combine + residual, H into now-free xm/xp
    combine_fused<<<((NMOL + NPROT)*HEADS + TB - 1)/TB, TB>>>(part1, part2, hm, hp, xm, xp);

    // --- 11: fused pooling + head
    pool_final<<<BB, 64>>>(xm, xp, mbatch, pbatch, fc1W, fc1b, fc2W, fc2b, out);
}

// round 17
// speedup vs baseline: 1.1617x; 1.1617x over previous
#include <cuda_runtime.h>
#include <math.h>

#define HID   64
#define HEADS 4
#define HDIM  16
#define NMOL  2048
#define NPROT 4096
#define EMOL  32768
#define EPROT 131072
#define BB    32
#define SPLITS 8
#define QT    128
#define KT    64

typedef unsigned long long ull;

// ---------------- scratch (device globals) -----------------------------------
__device__ float g_xm[NMOL*HID];
__device__ float g_xp[NPROT*HID];
__device__ float g_em[EMOL*HID];      // permuted (CSR slot order)
__device__ float g_ep[EPROT*HID];     // permuted
__device__ float g_hm[NMOL*HID];      // ping-pong partner of g_xm
__device__ float g_hp[NPROT*HID];
__device__ float g_q1[NMOL*HID];
__device__ float g_k1[NPROT*HID];
__device__ float g_v1[NPROT*HID];
__device__ float g_q2[NPROT*HID];
__device__ float g_k2[NMOL*HID];
__device__ float g_v2[NMOL*HID];
__device__ float g_part1[(size_t)NMOL*HEADS*SPLITS*18];
__device__ float g_part2[(size_t)NPROT*HEADS*SPLITS*18];
// CSR scratch (zero-initialized at load; scan re-zeroes cnt each run)
__device__ int g_mcnt[NMOL+1];
__device__ int g_moff[NMOL+1];
__device__ int g_mcur[NMOL];
__device__ int g_msrc[EMOL];
__device__ int g_mpos[EMOL];
__device__ int g_pcnt[NPROT+1];
__device__ int g_poff[NPROT+1];
__device__ int g_pcur[NPROT];
__device__ int g_psrc[EPROT];
__device__ int g_ppos[EPROT];

// ---------------- f32x2 helpers (flash only) ----------------------------------
__device__ __forceinline__ ull pk2(float a, float b) {
    ull r; asm("mov.b64 %0, {%1,%2};" : "=l"(r) : "f"(a), "f"(b)); return r;
}
__device__ __forceinline__ void upk2(float& a, float& b, ull r) {
    asm("mov.b64 {%0,%1}, %2;" : "=f"(a), "=f"(b) : "l"(r));
}
__device__ __forceinline__ ull ffma2(ull a, ull b, ull c) {
    ull d; asm("fma.rn.f32x2 %0, %1, %2, %3;" : "=l"(d) : "l"(a), "l"(b), "l"(c)); return d;
}
__device__ __forceinline__ ull fmul2(ull a, ull b) {
    ull d; asm("mul.rn.f32x2 %0, %1, %2;" : "=l"(d) : "l"(a), "l"(b)); return d;
}
union LD { float4 f4; ulonglong2 u2; };

// ---------------- CSR build: hist / scan / scatter ----------------------------
__global__ void hist_fused(const int* __restrict__ mdst, const int* __restrict__ pdst,
                           int* __restrict__ mcnt, int* __restrict__ pcnt) {
    int e = blockIdx.x*blockDim.x + threadIdx.x;
    if (e < EMOL) atomicAdd(&mcnt[mdst[e]], 1);
    else if (e < EMOL + EPROT) atomicAdd(&pcnt[pdst[e - EMOL]], 1);
}

__global__ void scan_fused(int* __restrict__ mcnt, int* __restrict__ moff, int* __restrict__ mcur,
                           int* __restrict__ pcnt, int* __restrict__ poff, int* __restrict__ pcur) {
    int* cnt; int* off; int* cur; int N;
    if (blockIdx.x == 0) { cnt = mcnt; off = moff; cur = mcur; N = NMOL; }
    else                 { cnt = pcnt; off = poff; cur = pcur; N = NPROT; }
    __shared__ int wsum[32];
    int t = threadIdx.x, lane = t & 31, wid = t >> 5;
    int base = t*4;
    int v[4];
    #pragma unroll
    for (int i = 0; i < 4; i++) v[i] = (base+i < N) ? cnt[base+i] : 0;
    #pragma unroll
    for (int i = 0; i < 4; i++) if (base+i < N) cnt[base+i] = 0;
    int local = v[0]+v[1]+v[2]+v[3];
    int sc = local;
    #pragma unroll
    for (int o = 1; o < 32; o <<= 1) {
        int x = __shfl_up_sync(~0u, sc, o);
        if (lane >= o) sc += x;
    }
    if (lane == 31) wsum[wid] = sc;
    __syncthreads();
    if (wid == 0) {
        int x = wsum[lane];
        #pragma unroll
        for (int o = 1; o < 32; o <<= 1) {
            int y = __shfl_up_sync(~0u, x, o);
            if (lane >= o) x += y;
        }
        wsum[lane] = x;
    }
    __syncthreads();
    int excl = sc - local + (wid ? wsum[wid-1] : 0);
    #pragma unroll
    for (int i = 0; i < 4; i++) {
        if (base+i < N) { off[base+i] = excl; cur[base+i] = excl; }
        excl += v[i];
    }
    if (t == 1023) off[N] = wsum[31];
}

__global__ void scatter_fused(const int* __restrict__ mei, const int* __restrict__ pei,
                              int* __restrict__ mcur, int* __restrict__ msrc, int* __restrict__ mpos,
                              int* __restrict__ pcur, int* __restrict__ psrc, int* __restrict__ ppos) {
    int e = blockIdx.x*blockDim.x + threadIdx.x;
    if (e < EMOL) {
        int p = atomicAdd(&mcur[mei[EMOL + e]], 1);
        msrc[p] = mei[e];
        mpos[e] = p;
    } else if (e < EMOL + EPROT) {
        int ee = e - EMOL;
        int p = atomicAdd(&pcur[pei[EPROT + ee]], 1);
        psrc[p] = pei[ee];
        ppos[ee] = p;
    }
}

// ---------------- fused embeddings: 64 rows/block, weights amortized ---------
struct EmbedArgs {
    const float* in[4]; const float* W[4]; const float* b[4];
    float* out[4]; const int* pos[4]; int K[4]; int ofs[5];
};

template<int K>
__device__ __forceinline__ void embed_body(const float* __restrict__ ins,
                                           const float* __restrict__ ws,
                                           int rl, int c, float4* acc) {
    #pragma unroll
    for (int k = 0; k < K; k++) {
        float4 w = ((const float4*)ws)[k*16 + c];
        #pragma unroll
        for (int j = 0; j < 4; j++) {
            float iv = ins[(rl + 16*j)*16 + k];
            acc[j].x = fmaf(iv, w.x, acc[j].x);
            acc[j].y = fmaf(iv, w.y, acc[j].y);
            acc[j].z = fmaf(iv, w.z, acc[j].z);
            acc[j].w = fmaf(iv, w.w, acc[j].w);
        }
    }
}

__global__ void embed_fused(EmbedArgs a) {
    __shared__ float ws[15*64];
    __shared__ float ins[64*16];   // 64 rows, K padded to stride 16
    __shared__ float bs[64];
    int bid = blockIdx.x;
    int t;
    if      (bid < a.ofs[1]) t = 0;
    else if (bid < a.ofs[2]) t = 1;
    else if (bid < a.ofs[3]) t = 2;
    else                     t = 3;
    int K = a.K[t];
    int rel = bid - a.ofs[t];
    int tid = threadIdx.x;
    for (int i = tid; i < K*64; i += 256) ws[i] = a.W[t][i];
    if (tid < 64) bs[tid] = a.b[t][tid];
    {   // coalesced stage of 64 input rows (64*K <= 960)
        const float* inb = a.in[t] + (size_t)rel*64*K;
        for (int i = tid; i < 64*K; i += 256) ins[(i/K)*16 + (i%K)] = inb[i];
    }
    __syncthreads();
    int c = tid & 15, rl = tid >> 4;
    float4 acc[4];
    #pragma unroll
    for (int j = 0; j < 4; j++) acc[j] = ((const float4*)bs)[c];
    if (K == 11)      embed_body<11>(ins, ws, rl, c, acc);
    else if (K == 15) embed_body<15>(ins, ws, rl, c, acc);
    else              embed_body<10>(ins, ws, rl, c, acc);
    const int* pos = a.pos[t];
    float4* outp = (float4*)a.out[t];
    #pragma unroll
    for (int j = 0; j < 4; j++) {
        int row = rel*64 + rl + 16*j;
        int orow = pos ? pos[row] : row;
        outp[(size_t)orow*16 + c] = acc[j];
    }
}

// ---------------- fused GINE layer: 512 threads, float2 gather + MLP ---------
struct GineArgs {
    const float* x[2]; const float* e[2];
    const int* off[2]; const int* srcs[2];
    const float* W1[2]; const float* b1[2]; const float* W2[2]; const float* b2[2];
    float* xout[2]; int nblk0;
};
__global__ void gine_fused(GineArgs a) {
    __shared__ float w1s[64*64];
    __shared__ float w2s[64*64];
    __shared__ float hs[16][64];
    __shared__ float ts[16][64];
    int g = (blockIdx.x < a.nblk0) ? 0 : 1;
    int bbase = ((g ? blockIdx.x - a.nblk0 : blockIdx.x)) * 16;
    int tid = threadIdx.x;     // 512
    for (int i = tid; i < 64*64; i += 512) { w1s[i] = a.W1[g][i]; w2s[i] = a.W2[g][i]; }
    const float* x    = a.x[g];
    const float* e    = a.e[g];
    const int*   off  = a.off[g];
    const int*   srcs = a.srcs[g];
    // gather: all 16 nodes concurrent, 32 threads/node, float2 per thread
    {
        int r = tid >> 5;          // node slot 0..15
        int c = tid & 31;          // float2 column 0..31
        int node = bbase + r;
        const float2* x2 = (const float2*)x;
        const float2* e2 = (const float2*)e;
        float2 acc = __ldg(x2 + (size_t)node*32 + c);
        int jb = off[node], je = off[node+1];
        #pragma unroll 8
        for (int j = jb; j < je; j++) {
            int s = __ldg(srcs + j);
            float2 xv = __ldg(x2 + (size_t)s*32 + c);
            float2 ev = __ldg(e2 + (size_t)j*32 + c);
            acc.x += fmaxf(xv.x + ev.x, 0.f);
            acc.y += fmaxf(xv.y + ev.y, 0.f);
        }
        ((float2*)hs[r])[c] = acc;
    }
    __syncthreads();
    // MLP: 16 rows x 32 col-pairs (float2 per thread)
    int r = tid >> 5, c = tid & 31;
    float2 acc = ((const float2*)a.b1[g])[c];
    #pragma unroll
    for (int k = 0; k < 64; k++) {
        float hv = hs[r][k];
        float2 w = ((const float2*)(w1s + k*64))[c];
        acc.x = fmaf(hv, w.x, acc.x);
        acc.y = fmaf(hv, w.y, acc.y);
    }
    acc.x = fmaxf(acc.x, 0.f); acc.y = fmaxf(acc.y, 0.f);
    ((float2*)ts[r])[c] = acc;
    __syncthreads();
    float2 acc2 = ((const float2*)a.b2[g])[c];
    #pragma unroll
    for (int k = 0; k < 64; k++) {
        float hv = ts[r][k];
        float2 w = ((const float2*)(w2s + k*64))[c];
        acc2.x = fmaf(hv, w.x, acc2.x);
        acc2.y = fmaf(hv, w.y, acc2.y);
    }
    acc2.x = fmaxf(acc2.x, 0.f); acc2.y = fmaxf(acc2.y, 0.f);
    ((float2*)(a.xout[g] + (size_t)(bbase + r)*HID))[c] = acc2;
}

// ---------------- fused QKV linears: 64 rows/block, 4x4 register tile --------
struct QKVArgs {
    const float* in[6]; const float* W[6]; const float* b[6];
    float* out[6]; int ofs[7];
};
__global__ void qkv_fused(QKVArgs a) {
    __shared__ float ws[64*64];
    __shared__ float ins[64*64];
    __shared__ float bs[64];
    int bid = blockIdx.x;
    int t = 5;
    #pragma unroll
    for (int i = 5; i >= 1; i--) if (bid < a.ofs[i]) t = i - 1;
    int rel = bid - a.ofs[t];
    int tid = threadIdx.x;
    {
        const float4* wg = (const float4*)a.W[t];
        float4* wsh = (float4*)ws;
        #pragma unroll
        for (int i = 0; i < 4; i++) wsh[tid + 256*i] = wg[tid + 256*i];
    }
    if (tid < 64) bs[tid] = a.b[t][tid];
    {
        const float4* ig = (const float4*)(a.in[t] + (size_t)rel*64*64);
        float4* ish = (float4*)ins;
        #pragma unroll
        for (int i = 0; i < 4; i++) ish[tid + 256*i] = ig[tid + 256*i];
    }
    __syncthreads();
    int c = tid & 15, rl = tid >> 4;
    float4 acc[4];
    #pragma unroll
    for (int j = 0; j < 4; j++) acc[j] = ((const float4*)bs)[c];
    #pragma unroll 16
    for (int k = 0; k < 64; k++) {
        float4 w = ((const float4*)ws)[k*16 + c];
        #pragma unroll
        for (int j = 0; j < 4; j++) {
            float iv = ins[(rl + 16*j)*64 + k];
            acc[j].x = fmaf(iv, w.x, acc[j].x);
            acc[j].y = fmaf(iv, w.y, acc[j].y);
            acc[j].z = fmaf(iv, w.z, acc[j].z);
            acc[j].w = fmaf(iv, w.w, acc[j].w);
        }
    }
    float4* outp = (float4*)a.out[t];
    #pragma unroll
    for (int j = 0; j < 4; j++)
        outp[(size_t)(rel*64 + rl + 16*j)*16 + c] = acc[j];
}

// ---------------- flash attention: 4-key batched max, base-2, f32x2 ----------
__global__ void flash_fused(const float* __restrict__ Q1, const float* __restrict__ K1,
                            const float* __restrict__ V1, const float* __restrict__ Q2,
                            const float* __restrict__ K2, const float* __restrict__ V2,
                            float* __restrict__ part1, float* __restrict__ part2) {
    __shared__ float4 sk[KT][4];
    __shared__ float4 sv[KT][4];
    const float *Q, *K, *V; float* part; int Nk, qblk;
    if (blockIdx.x < NMOL/QT) { Q = Q1; K = K1; V = V1; part = part1; Nk = NPROT; qblk = blockIdx.x; }
    else                      { Q = Q2; K = K2; V = V2; part = part2; Nk = NMOL;  qblk = blockIdx.x - NMOL/QT; }
    int h  = blockIdx.y;
    int sp = blockIdx.z;
    int chunk = Nk / SPLITS;
    int q  = qblk*QT + threadIdx.x;
    int k0 = sp*chunk;
    int k1 = k0 + chunk;
    const float QSCALE = 0.25f * 1.4426950408889634f;   // 1/sqrt(16) * log2(e)
    ull q2[8];
    {
        const float4* qp = (const float4*)(Q + (size_t)q*HID + h*HDIM);
        #pragma unroll
        for (int i = 0; i < 4; i++) {
            float4 tq = qp[i];
            q2[2*i]   = pk2(tq.x*QSCALE, tq.y*QSCALE);
            q2[2*i+1] = pk2(tq.z*QSCALE, tq.w*QSCALE);
        }
    }
    float m = -1e30f, l = 0.f;      // m in log2 domain
    ull o2[8];
    #pragma unroll
    for (int i = 0; i < 8; i++) o2[i] = 0ull;

    for (int kt = k0; kt < k1; kt += KT) {
        __syncthreads();
        for (int idx = threadIdx.x; idx < KT*4; idx += QT) {
            int row = idx >> 2, c = idx & 3;
            sk[row][c] = ((const float4*)(K + (size_t)(kt+row)*HID + h*HDIM))[c];
            sv[row][c] = ((const float4*)(V + (size_t)(kt+row)*HID + h*HDIM))[c];
        }
        __syncthreads();
        for (int jj = 0; jj < KT; jj += 4) {
            float sc[4];
            #pragma unroll
            for (int t = 0; t < 4; t++) {
                LD kr[4];
                #pragma unroll
                for (int c = 0; c < 4; c++) kr[c].f4 = sk[jj+t][c];
                ull acc = 0ull;
                #pragma unroll
                for (int c = 0; c < 4; c++) {
                    acc = ffma2(q2[2*c],   kr[c].u2.x, acc);
                    acc = ffma2(q2[2*c+1], kr[c].u2.y, acc);
                }
                float lo, hi; upk2(lo, hi, acc);
                sc[t] = lo + hi;                   // log2 domain
            }
            float mx = fmaxf(fmaxf(sc[0], sc[1]), fmaxf(sc[2], sc[3]));
            if (mx > m) {
                float alpha = exp2f(m - mx);
                l *= alpha;
                ull a2 = pk2(alpha, alpha);
                #pragma unroll
                for (int i = 0; i < 8; i++) o2[i] = fmul2(o2[i], a2);
                m = mx;
            }
            #pragma unroll
            for (int t = 0; t < 4; t++) {
                float p = exp2f(sc[t] - m);
                l += p;
                ull p2 = pk2(p, p);
                #pragma unroll
                for (int c = 0; c < 4; c++) {
                    LD vr; vr.f4 = sv[jj+t][c];
                    o2[2*c]   = ffma2(p2, vr.u2.x, o2[2*c]);
                    o2[2*c+1] = ffma2(p2, vr.u2.y, o2[2*c+1]);
                }
            }
        }
    }
    float* pp = part + (((size_t)q*HEADS + h)*SPLITS + sp)*18;
    pp[0] = m; pp[1] = l;
    #pragma unroll
    for (int i = 0; i < 8; i++) upk2(pp[2+2*i], pp[3+2*i], o2[i]);
}

// ---------------- combine split-KV partials + residual (base-2 domain) -------
__global__ void combine_fused(const float* __restrict__ part1, const float* __restrict__ part2,
                              const float* __restrict__ xm, const float* __restrict__ xp,
                              float* __restrict__ Hm, float* __restrict__ Hp) {
    int idx = blockIdx.x*blockDim.x + threadIdx.x;
    const float* part; const float* x; float* H;
    if (idx < NMOL*HEADS) { part = part1; x = xm; H = Hm; }
    else { idx -= NMOL*HEADS; if (idx >= NPROT*HEADS) return; part = part2; x = xp; H = Hp; }
    int q = idx >> 2, h = idx & 3;
    const float* pp = part + (size_t)idx*SPLITS*18;
    float M = -1e30f;
    #pragma unroll
    for (int sp = 0; sp < SPLITS; sp++) M = fmaxf(M, pp[sp*18]);
    float L = 0.f;
    float O[HDIM];
    #pragma unroll
    for (int i = 0; i < HDIM; i++) O[i] = 0.f;
    #pragma unroll
    for (int sp = 0; sp < SPLITS; sp++) {
        float w = exp2f(pp[sp*18] - M);
        L += w * pp[sp*18 + 1];
        #pragma unroll
        for (int i = 0; i < HDIM; i++) O[i] = fmaf(w, pp[sp*18 + 2 + i], O[i]);
    }
    float inv = 1.f / L;
    #pragma unroll
    for (int i = 0; i < HDIM; i++)
        H[(size_t)q*HID + h*HDIM + i] = x[(size_t)q*HID + h*HDIM + i] + O[i]*inv;
}

// ---------------- fused pooling + head MLP: one block per batch element ------
__global__ void pool_final(const float* __restrict__ Hm, const float* __restrict__ Hp,
                           const int* __restrict__ mbatch, const int* __restrict__ pbatch,
                           const float* __restrict__ fc1W, const float* __restrict__ fc1b,
                           const float* __restrict__ fc2W, const float* __restrict__ fc2b,
                           float* __restrict__ out) {
    __shared__ float zs[2*HID];
    __shared__ float wpart[2];
    int b = blockIdx.x;
    int f = threadIdx.x;   // 64
    {
        int lo = 0, hi = NMOL;
        while (lo < hi) { int mid = (lo+hi) >> 1; if (mbatch[mid] < b) lo = mid+1; else hi = mid; }
        int lo2 = lo, hi2 = NMOL;
        while (lo2 < hi2) { int mid = (lo2+hi2) >> 1; if (mbatch[mid] < b+1) lo2 = mid+1; else hi2 = mid; }
        float s = 0.f;
        for (int r = lo; r < lo2; r++) s += Hm[(size_t)r*HID + f];
        zs[f] = s / fmaxf((float)(lo2 - lo), 1.f);
    }
    {
        int lo = 0, hi = NPROT;
        while (lo < hi) { int mid = (lo+hi) >> 1; if (pbatch[mid] < b) lo = mid+1; else hi = mid; }
        int lo2 = lo, hi2 = NPROT;
        while (lo2 < hi2) { int mid = (lo2+hi2) >> 1; if (pbatch[mid] < b+1) lo2 = mid+1; else hi2 = mid; }
        float s = 0.f;
        for (int r = lo; r < lo2; r++) s += Hp[(size_t)r*HID + f];
        zs[HID + f] = s / fmaxf((float)(lo2 - lo), 1.f);
    }
    __syncthreads();
    float acc = fc1b[f];
    #pragma unroll 8
    for (int k = 0; k < 2*HID; k++) acc = fmaf(zs[k], fc1W[k*HID + f], acc);
    float r = fmaxf(acc, 0.f) * fc2W[f];
    #pragma unroll
    for (int off = 16; off; off >>= 1) r += __shfl_down_sync(0xffffffffu, r, off);
    if ((f & 31) == 0) wpart[f >> 5] = r;
    __syncthreads();
    if (f == 0) out[b] = 1.f / (1.f + __expf(-(wpart[0] + wpart[1] + fc2b[0])));
}

// =============================================================================
extern "C" void kernel_launch(void* const* d_in, const int* in_sizes, int n_in,
                              void* d_out, int out_size) {
    static const int sig_map[32]   = { 0,1,2,3, 4,5,6,7, 8,9,10,11, 12,13,14,15,
                                       16,17,18,19, 20,21,22,23, 24,25,26,27, 28,29,30,31 };
    static const int setup_map[32] = { 0,1,2,3, 8,9,10,11, 12,13,14,15, 16,17,18,19,
                                       20,21,22,23, 24,25,26,27, 28,29,30,31, 4,5,6,7 };
    const int* map = (in_sizes[4] == 2*EMOL) ? setup_map : sig_map;
    #define IN(p) ((const float*)d_in[map[(p)]])
    #define INI(p) ((const int*)d_in[map[(p)]])

    const float *mol_x = IN(0), *prot_x = IN(1), *mol_eattr = IN(2), *prot_eattr = IN(3);
    const float *nlmW = IN(4), *nlmb = IN(5), *nlpW = IN(6), *nlpb = IN(7);
    const float *elmW = IN(8), *elmb = IN(9), *elpW = IN(10), *elpb = IN(11);
    const float *mcW1 = IN(12), *mcb1 = IN(13), *mcW2 = IN(14), *mcb2 = IN(15);
    const float *pcW1 = IN(16), *pcb1 = IN(17), *pcW2 = IN(18), *pcb2 = IN(19);
    const float *ampW = IN(20), *ampb = IN(21), *apmW = IN(22), *apmb = IN(23);
    const float *fc1W = IN(24), *fc1b = IN(25), *fc2W = IN(26), *fc2b = IN(27);
    const int *mei = INI(28), *pei = INI(29), *mbatch = INI(30), *pbatch = INI(31);
    float* out = (float*)d_out;

    float *xm, *xp, *em, *ep, *hm, *hp, *q1, *k1, *v1, *q2, *k2, *v2, *part1, *part2;
    int *mcnt, *moff, *mcur, *msrc, *mpos, *pcnt, *poff, *pcur, *psrc, *ppos;
    cudaGetSymbolAddress((void**)&xm, g_xm);
    cudaGetSymbolAddress((void**)&xp, g_xp);
    cudaGetSymbolAddress((void**)&em, g_em);
    cudaGetSymbolAddress((void**)&ep, g_ep);
    cudaGetSymbolAddress((void**)&hm, g_hm);
    cudaGetSymbolAddress((void**)&hp, g_hp);
    cudaGetSymbolAddress((void**)&q1, g_q1);
    cudaGetSymbolAddress((void**)&k1, g_k1);
    cudaGetSymbolAddress((void**)&v1, g_v1);
    cudaGetSymbolAddress((void**)&q2, g_q2);
    cudaGetSymbolAddress((void**)&k2, g_k2);
    cudaGetSymbolAddress((void**)&v2, g_v2);
    cudaGetSymbolAddress((void**)&part1, g_part1);
    cudaGetSymbolAddress((void**)&part2, g_part2);
    cudaGetSymbolAddress((void**)&mcnt, g_mcnt);
    cudaGetSymbolAddress((void**)&moff, g_moff);
    cudaGetSymbolAddress((void**)&mcur, g_mcur);
    cudaGetSymbolAddress((void**)&msrc, g_msrc);
    cudaGetSymbolAddress((void**)&mpos, g_mpos);
    cudaGetSymbolAddress((void**)&pcnt, g_pcnt);
    cudaGetSymbolAddress((void**)&poff, g_poff);
    cudaGetSymbolAddress((void**)&pcur, g_pcur);
    cudaGetSymbolAddress((void**)&psrc, g_psrc);
    cudaGetSymbolAddress((void**)&ppos, g_ppos);

    const int TB = 256;

    // --- 1-3: CSR build
    hist_fused<<<(EMOL + EPROT + TB - 1)/TB, TB>>>(mei + EMOL, pei + EPROT, mcnt, pcnt);
    scan_fused<<<2, 1024>>>(mcnt, moff, mcur, pcnt, poff, pcur);
    scatter_fused<<<(EMOL + EPROT + TB - 1)/TB, TB>>>(mei, pei, mcur, msrc, mpos, pcur, psrc, ppos);

    // --- 4: all embeddings, 64 rows/block (edge outputs in CSR order)
    {
        EmbedArgs a;
        a.in[0] = mol_x;     a.W[0] = nlmW; a.b[0] = nlmb; a.out[0] = xm; a.pos[0] = nullptr; a.K[0] = 11;
        a.in[1] = prot_x;    a.W[1] = nlpW; a.b[1] = nlpb; a.out[1] = xp; a.pos[1] = nullptr; a.K[1] = 15;
        a.in[2] = mol_eattr; a.W[2] = elmW; a.b[2] = elmb; a.out[2] = em; a.pos[2] = mpos;    a.K[2] = 10;
        a.in[3] = prot_eattr;a.W[3] = elpW; a.b[3] = elpb; a.out[3] = ep; a.pos[3] = ppos;    a.K[3] = 10;
        a.ofs[0] = 0; a.ofs[1] = NMOL/64; a.ofs[2] = a.ofs[1] + NPROT/64;
        a.ofs[3] = a.ofs[2] + EMOL/64; a.ofs[4] = a.ofs[3] + EPROT/64;
        embed_fused<<<a.ofs[4], TB>>>(a);
    }

    // --- 5-7: GINE layers, 512 threads/block, ping-pong buffers (in != out)
    for (int l = 0; l < 3; l++) {
        const float* im = (l & 1) ? hm : xm;
        const float* ip = (l & 1) ? hp : xp;
        float* om = (l & 1) ? xm : hm;
        float* op = (l & 1) ? xp : hp;
        GineArgs a;
        a.x[0] = im; a.e[0] = em; a.off[0] = moff; a.srcs[0] = msrc;
        a.W1[0] = mcW1 + l*4096; a.b1[0] = mcb1 + l*64; a.W2[0] = mcW2 + l*4096; a.b2[0] = mcb2 + l*64;
        a.xout[0] = om;
        a.x[1] = ip; a.e[1] = ep; a.off[1] = poff; a.srcs[1] = psrc;
        a.W1[1] = pcW1 + l*4096; a.b1[1] = pcb1 + l*64; a.W2[1] = pcW2 + l*4096; a.b2[1] = pcb2 + l*64;
        a.xout[1] = op;
        a.nblk0 = NMOL/16;
        gine_fused<<<NMOL/16 + NPROT/16, 512>>>(a);
    }
    // post-conv features: hm (mol), hp (prot)

    // --- 8: all six QKV linears, 64 rows/block
    {
        QKVArgs a;
        a.in[0] = hm; a.W[0] = ampW;        a.b[0] = ampb;       a.out[0] = q1;
        a.in[1] = hp; a.W[1] = ampW + 4096; a.b[1] = ampb + 64;  a.out[1] = k1;
        a.in[2] = hp; a.W[2] = ampW + 8192; a.b[2] = ampb + 128; a.out[2] = v1;
        a.in[3] = hp; a.W[3] = apmW;        a.b[3] = apmb;       a.out[3] = q2;
        a.in[4] = hm; a.W[4] = apmW + 4096; a.b[4] = apmb + 64;  a.out[4] = k2;
        a.in[5] = hm; a.W[5] = apmW + 8192; a.b[5] = apmb + 128; a.out[5] = v2;
        int nb[6] = { NMOL/64, NPROT/64, NPROT/64, NPROT/64, NMOL/64, NMOL/64 };
        a.ofs[0] = 0;
        for (int i = 0; i < 6; i++) a.ofs[i+1] = a.ofs[i] + nb[i];
        qkv_fused<<<a.ofs[6], TB>>>(a);
    }

    // --- 9: flash attention, both directions
    {
        dim3 grid(NMOL/QT + NPROT/QT, HEADS, SPLITS);
        flash_fused<<<grid, QT>>>(q1, k1, v1, q2, k2, v2, part1, part2);
    }

    // --- 10: combine + residual, H into now-free xm/xp
    combine_fused<<<((NMOL + NPROT)*HEADS + TB - 1)/TB, TB>>>(part1, part2, hm, hp, xm, xp);

    // --- 11: fused pooling + head
    pool_final<<<BB, 64>>>(xm, xp, mbatch, pbatch, fc1W, fc1b, fc2W, fc2b, out);
}